// round 8
// baseline (speedup 1.0000x reference)
#include <cuda_runtime.h>

// StatelessConvLIF: fused 3x3 SAME conv (fp32) + LIF scan over T=8.
// x: [8,16,64,64,64] fp32, W: [128,64,3,3] fp32, out spikes: [8,16,128,64,64] fp32.
//
// Strategy: compute-bound fp32 conv using packed fma.rn.f32x2 (2x FFMA rate on
// sm_103a, PTX-only). Block = 32x32 spatial tile x 8 cout; thread = 4 pixels x
// 8 cout. v-state carried in registers across the T loop; x streamed through
// smem in 8-channel chunks; weights pre-duplicated {w,w} in smem.

#define THREADS 256
#define TILE_H  32
#define TILE_W  32
#define CHUNK   8
#define XSTRIDE 36          // 34 cols padded to 36 (16B-aligned rows, conflict-free)
#define NCO     8           // couts per block
#define T_STEPS 8
#define BATCH   16
#define CIN     64
#define COUT    128
#define HW      64

typedef unsigned long long ull;

__device__ __forceinline__ ull pk2(float lo, float hi) {
    ull r; asm("mov.b64 %0, {%1, %2};" : "=l"(r) : "f"(lo), "f"(hi)); return r;
}
__device__ __forceinline__ void upk2(ull a, float& lo, float& hi) {
    asm("mov.b64 {%0, %1}, %2;" : "=f"(lo), "=f"(hi) : "l"(a));
}
__device__ __forceinline__ void ffma2(ull& d, ull a, ull b) {
    asm("fma.rn.f32x2 %0, %1, %2, %0;" : "+l"(d) : "l"(a), "l"(b));
}

__global__ __launch_bounds__(THREADS, 2)
void convlif_kernel(const float* __restrict__ x,
                    const float* __restrict__ w,
                    float* __restrict__ out)
{
    extern __shared__ float smem[];
    float* xs = smem;                                    // [CHUNK][34][XSTRIDE]
    ull*   ws = (ull*)(smem + CHUNK * 34 * XSTRIDE);     // [NCO][CIN][10] {w,w} pairs

    const int tid = threadIdx.x;
    const int tx  = tid & 7;        // col-group: 4 pixels at w0 + 4*tx
    const int ty  = tid >> 3;       // row within tile: 0..31
    const int h0  = (blockIdx.x >> 1) * TILE_H;
    const int w0  = (blockIdx.x & 1) * TILE_W;
    const int b   = blockIdx.y;
    const int cg  = blockIdx.z;     // cout group

    // Load weights once, duplicated into {w,w} 64-bit pairs (pair stride 10 -> 80B, 16B aligned).
    {
        const float* wg = w + (size_t)cg * NCO * CIN * 9;
        for (int i = tid; i < NCO * CIN * 9; i += THREADS) {
            int cocin = i / 9, k = i - cocin * 9;
            float wv = wg[i];
            ws[cocin * 10 + k] = pk2(wv, wv);
        }
    }

    // Membrane potential, packed per pixel-pair: v01 = {px0,px1}, v23 = {px2,px3}.
    ull v01[NCO], v23[NCO];
#pragma unroll
    for (int co = 0; co < NCO; co++) { v01[co] = 0ull; v23[co] = 0ull; }

#pragma unroll 1
    for (int t = 0; t < T_STEPS; t++) {
        ull a01[NCO], a23[NCO];
#pragma unroll
        for (int co = 0; co < NCO; co++) { a01[co] = 0ull; a23[co] = 0ull; }

#pragma unroll 1
        for (int ch = 0; ch < CIN / CHUNK; ch++) {
            __syncthreads();   // protects previous chunk's reads (and weight init on iter 0)
            const float* xb = x + (((size_t)t * BATCH + b) * CIN + ch * CHUNK) * (HW * HW);
            for (int e = tid; e < CHUNK * 34 * 34; e += THREADS) {
                int c   = e / (34 * 34);
                int r   = e - c * (34 * 34);
                int row = r / 34;
                int col = r - row * 34;
                int gh  = h0 + row - 1;
                int gw  = w0 + col - 1;
                float val = 0.f;
                if ((unsigned)gh < (unsigned)HW && (unsigned)gw < (unsigned)HW)
                    val = xb[c * (HW * HW) + gh * HW + gw];
                xs[(c * 34 + row) * XSTRIDE + col] = val;
            }
            __syncthreads();

#pragma unroll 1
            for (int c = 0; c < CHUNK; c++) {
                // Load 3x6 input window (float4 + float2, conflict-free), pack sliding pairs.
                const float* xr = xs + (c * 34 + ty) * XSTRIDE + tx * 4;
                ull P[3][5];
#pragma unroll
                for (int dy = 0; dy < 3; dy++) {
                    float4 a4 = *(const float4*)(xr + dy * XSTRIDE);
                    float2 b2 = *(const float2*)(xr + dy * XSTRIDE + 4);
                    P[dy][0] = pk2(a4.x, a4.y);
                    P[dy][1] = pk2(a4.y, a4.z);
                    P[dy][2] = pk2(a4.z, a4.w);
                    P[dy][3] = pk2(a4.w, b2.x);
                    P[dy][4] = pk2(b2.x, b2.y);
                }
                const int cin = ch * CHUNK + c;
#pragma unroll
                for (int co = 0; co < NCO; co++) {
                    const ull* wp = ws + (co * CIN + cin) * 10;
                    ull wq[9];
#pragma unroll
                    for (int k = 0; k < 9; k++) wq[k] = wp[k];
#pragma unroll
                    for (int ky = 0; ky < 3; ky++)
#pragma unroll
                        for (int kx = 0; kx < 3; kx++) {
                            ffma2(a01[co], P[ky][kx],     wq[ky * 3 + kx]);
                            ffma2(a23[co], P[ky][kx + 2], wq[ky * 3 + kx]);
                        }
                }
            }
        }

        // LIF update + spike store (matches reference op order: v += (z - v)/2).
#pragma unroll
        for (int co = 0; co < NCO; co++) {
            float z0, z1, z2, z3, u0, u1, u2, u3;
            upk2(a01[co], z0, z1);
            upk2(a23[co], z2, z3);
            upk2(v01[co], u0, u1);
            upk2(v23[co], u2, u3);
            u0 += (z0 - u0) * 0.5f;
            u1 += (z1 - u1) * 0.5f;
            u2 += (z2 - u2) * 0.5f;
            u3 += (z3 - u3) * 0.5f;
            float4 s;
            s.x = (u0 >= 1.0f) ? 1.f : 0.f;  if (u0 >= 1.0f) u0 = 0.f;
            s.y = (u1 >= 1.0f) ? 1.f : 0.f;  if (u1 >= 1.0f) u1 = 0.f;
            s.z = (u2 >= 1.0f) ? 1.f : 0.f;  if (u2 >= 1.0f) u2 = 0.f;
            s.w = (u3 >= 1.0f) ? 1.f : 0.f;  if (u3 >= 1.0f) u3 = 0.f;
            v01[co] = pk2(u0, u1);
            v23[co] = pk2(u2, u3);
            size_t o = ((((size_t)t * BATCH + b) * COUT + cg * NCO + co) * HW + (h0 + ty)) * HW
                     + (w0 + tx * 4);
            *(float4*)(out + o) = s;
        }
    }
}

extern "C" void kernel_launch(void* const* d_in, const int* in_sizes, int n_in,
                              void* d_out, int out_size)
{
    const float* x = (const float*)d_in[0];
    const float* w = (const float*)d_in[1];
    float* out     = (float*)d_out;

    const int smem_bytes = CHUNK * 34 * XSTRIDE * 4   // x tile: 39,168 B
                         + NCO * CIN * 10 * 8;        // weight pairs: 40,960 B -> 80,128 B
    cudaFuncSetAttribute(convlif_kernel,
                         cudaFuncAttributeMaxDynamicSharedMemorySize, smem_bytes);

    dim3 grid(4 /* 2x2 spatial tiles */, BATCH, COUT / NCO);
    convlif_kernel<<<grid, THREADS, smem_bytes>>>(x, w, out);
}

// round 10
// speedup vs baseline: 1.2034x; 1.2034x over previous
#include <cuda_runtime.h>

// StatelessConvLIF: fused 3x3 SAME conv (fp32) + LIF scan over T=8.
// x: [8,16,64,64,64] fp32, W: [128,64,3,3] fp32, out spikes: [8,16,128,64,64] fp32.
//
// R10 (= R9 re-bench; prior run died on device-init infra error):
// cp.async double-buffered x loader (CHUNK=4, 2 buffers) overlapping global
// loads with compute; division-free loader indexing. Conv math (packed
// fma.rn.f32x2, cin/ky/kx order) is bit-identical to the R8 passing kernel.

#define THREADS 256
#define CHUNK   4
#define XSTRIDE 36          // 34 cols padded to 36
#define XBUF    (CHUNK * 34 * XSTRIDE)   // floats per buffer = 4896
#define NCO     8
#define T_STEPS 8
#define BATCH   16
#define CIN     64
#define COUT    128
#define HW      64

typedef unsigned long long ull;

__device__ __forceinline__ ull pk2(float lo, float hi) {
    ull r; asm("mov.b64 %0, {%1, %2};" : "=l"(r) : "f"(lo), "f"(hi)); return r;
}
__device__ __forceinline__ void upk2(ull a, float& lo, float& hi) {
    asm("mov.b64 {%0, %1}, %2;" : "=f"(lo), "=f"(hi) : "l"(a));
}
__device__ __forceinline__ void ffma2(ull& d, ull a, ull b) {
    asm("fma.rn.f32x2 %0, %1, %2, %0;" : "+l"(d) : "l"(a), "l"(b));
}
__device__ __forceinline__ void cp4(unsigned dst, const float* src, unsigned sz) {
    asm volatile("cp.async.ca.shared.global [%0], [%1], 4, %2;"
                 :: "r"(dst), "l"(src), "r"(sz));
}
__device__ __forceinline__ void cp_commit() {
    asm volatile("cp.async.commit_group;");
}
__device__ __forceinline__ void cp_wait0() {
    asm volatile("cp.async.wait_group 0;");
}

__global__ __launch_bounds__(THREADS, 2)
void convlif_kernel(const float* __restrict__ x,
                    const float* __restrict__ w,
                    float* __restrict__ out)
{
    extern __shared__ float smem[];
    float* xs0 = smem;                    // buffer 0: [CHUNK][34][XSTRIDE]
    float* xs1 = smem + XBUF;             // buffer 1
    ull*   ws  = (ull*)(smem + 2 * XBUF); // [NCO][CIN][10] {w,w} pairs

    const int tid  = threadIdx.x;
    const int lane = tid & 31;
    const int warp = tid >> 5;
    const int tx   = tid & 7;
    const int ty   = tid >> 3;
    const int h0   = (blockIdx.x >> 1) * 32;
    const int w0   = (blockIdx.x & 1) * 32;
    const int b    = blockIdx.y;
    const int cg   = blockIdx.z;

    // Weights -> smem as {w,w} pairs (visible after first loop barrier).
    {
        const float* wg = w + (size_t)cg * NCO * CIN * 9;
        for (int i = tid; i < NCO * CIN * 9; i += THREADS) {
            int cocin = i / 9, k = i - cocin * 9;
            float wv = wg[i];
            ws[cocin * 10 + k] = pk2(wv, wv);
        }
    }

    // Loader geometry (division-free): warp covers (c = warp>>1), 17 rows
    // starting at (warp&1)*17; lane covers col = lane, lanes 0/1 also 32/33.
    const int lc    = warp >> 1;               // chunk-local channel 0..3
    const int lrow0 = (warp & 1) * 17;         // 0 or 17
    const int gw_m  = w0 + lane - 1;           // main col, global
    const unsigned okw_m = ((unsigned)gw_m < HW) ? 4u : 0u;
    const int gwc_m = (gw_m < 0) ? 0 : (gw_m >= HW ? HW - 1 : gw_m);
    const int gw_t  = w0 + 32 + lane - 1;      // tail col (lanes 0,1)
    const unsigned okw_t = ((unsigned)gw_t < HW) ? 4u : 0u;
    const int gwc_t = (gw_t >= HW) ? HW - 1 : gw_t;

    unsigned smem_u32;
    {
        void* p = smem;
        asm("{ .reg .u64 t; cvta.to.shared.u64 t, %1; cvt.u32.u64 %0, t; }"
            : "=r"(smem_u32) : "l"(p));
    }

    // Prefetch one chunk: global index g in [0,128) = t*16 + ch (4 cins each).
    auto prefetch = [&](int g, int buf) {
        if (g < T_STEPS * 16) {
            const int t  = g >> 4;
            const int ch = g & 15;
            const float* xb = x + (((size_t)t * BATCH + b) * CIN + ch * CHUNK + lc) * (HW * HW);
            unsigned dst0 = smem_u32 + (unsigned)(buf * XBUF + lc * 34 * XSTRIDE) * 4u;
#pragma unroll 1
            for (int j = 0; j < 17; j++) {
                const int row = lrow0 + j;
                const int gh  = h0 + row - 1;
                const unsigned okh = ((unsigned)gh < HW) ? 4u : 0u;
                const int ghc = (gh < 0) ? 0 : (gh >= HW ? HW - 1 : gh);
                const float* srow = xb + ghc * HW;
                unsigned drow = dst0 + (unsigned)(row * XSTRIDE) * 4u;
                cp4(drow + (unsigned)lane * 4u, srow + gwc_m, okh & okw_m);
                if (lane < 2)
                    cp4(drow + (unsigned)(32 + lane) * 4u, srow + gwc_t, okh & okw_t);
            }
        }
        cp_commit();
    };

    prefetch(0, 0);

    ull v01[NCO], v23[NCO];
#pragma unroll
    for (int co = 0; co < NCO; co++) { v01[co] = 0ull; v23[co] = 0ull; }

    ull a01[NCO], a23[NCO];
#pragma unroll
    for (int co = 0; co < NCO; co++) { a01[co] = 0ull; a23[co] = 0ull; }

#pragma unroll 1
    for (int g = 0; g < T_STEPS * 16; g++) {
        cp_wait0();            // this thread's chunk-g data in smem
        __syncthreads();       // all threads' data in; prev buffer free

        prefetch(g + 1, (g + 1) & 1);

        const float* xs = (g & 1) ? xs1 : xs0;
        const int cin0 = (g & 15) * CHUNK;

#pragma unroll 1
        for (int c = 0; c < CHUNK; c++) {
            const float* xr = xs + (c * 34 + ty) * XSTRIDE + tx * 4;
            ull P[3][5];
#pragma unroll
            for (int dy = 0; dy < 3; dy++) {
                float4 a4 = *(const float4*)(xr + dy * XSTRIDE);
                float2 b2 = *(const float2*)(xr + dy * XSTRIDE + 4);
                P[dy][0] = pk2(a4.x, a4.y);
                P[dy][1] = pk2(a4.y, a4.z);
                P[dy][2] = pk2(a4.z, a4.w);
                P[dy][3] = pk2(a4.w, b2.x);
                P[dy][4] = pk2(b2.x, b2.y);
            }
            const int cin = cin0 + c;
#pragma unroll
            for (int co = 0; co < NCO; co++) {
                const ull* wp = ws + (co * CIN + cin) * 10;
                ull wq[9];
#pragma unroll
                for (int k = 0; k < 9; k++) wq[k] = wp[k];
#pragma unroll
                for (int ky = 0; ky < 3; ky++)
#pragma unroll
                    for (int kx = 0; kx < 3; kx++) {
                        ffma2(a01[co], P[ky][kx],     wq[ky * 3 + kx]);
                        ffma2(a23[co], P[ky][kx + 2], wq[ky * 3 + kx]);
                    }
            }
        }

        if ((g & 15) == 15) {
            const int t = g >> 4;
            // LIF update + spike store (reference op order: v += (z - v)/2).
#pragma unroll
            for (int co = 0; co < NCO; co++) {
                float z0, z1, z2, z3, u0, u1, u2, u3;
                upk2(a01[co], z0, z1);
                upk2(a23[co], z2, z3);
                upk2(v01[co], u0, u1);
                upk2(v23[co], u2, u3);
                u0 += (z0 - u0) * 0.5f;
                u1 += (z1 - u1) * 0.5f;
                u2 += (z2 - u2) * 0.5f;
                u3 += (z3 - u3) * 0.5f;
                float4 s;
                s.x = (u0 >= 1.0f) ? 1.f : 0.f;  if (u0 >= 1.0f) u0 = 0.f;
                s.y = (u1 >= 1.0f) ? 1.f : 0.f;  if (u1 >= 1.0f) u1 = 0.f;
                s.z = (u2 >= 1.0f) ? 1.f : 0.f;  if (u2 >= 1.0f) u2 = 0.f;
                s.w = (u3 >= 1.0f) ? 1.f : 0.f;  if (u3 >= 1.0f) u3 = 0.f;
                v01[co] = pk2(u0, u1);
                v23[co] = pk2(u2, u3);
                a01[co] = 0ull;
                a23[co] = 0ull;
                size_t o = ((((size_t)t * BATCH + b) * COUT + cg * NCO + co) * HW + (h0 + ty)) * HW
                         + (w0 + tx * 4);
                *(float4*)(out + o) = s;
            }
        }
    }
}

extern "C" void kernel_launch(void* const* d_in, const int* in_sizes, int n_in,
                              void* d_out, int out_size)
{
    const float* x = (const float*)d_in[0];
    const float* w = (const float*)d_in[1];
    float* out     = (float*)d_out;

    const int smem_bytes = 2 * XBUF * 4        // x double buffer: 39,168 B
                         + NCO * CIN * 10 * 8; // weight pairs:     40,960 B  -> 80,128 B
    cudaFuncSetAttribute(convlif_kernel,
                         cudaFuncAttributeMaxDynamicSharedMemorySize, smem_bytes);

    dim3 grid(4 /* 2x2 spatial tiles */, BATCH, COUT / NCO);
    convlif_kernel<<<grid, THREADS, smem_bytes>>>(x, w, out);
}